// round 15
// baseline (speedup 1.0000x reference)
#include <cuda_runtime.h>
#include <cuda_fp16.h>
#include <float.h>
#include <string.h>

// Problem constants
#define NWIN   4096
#define NTOK   49
#define CDIM   384
#define HEADS  12
#define HDIM   32
#define MROWS  (NWIN * NTOK)        // 200704
#define QKVCOL (3 * CDIM)           // 1152

// Scratch (allocation-free rule: __device__ globals)
__device__ __half g_xh    [(size_t)MROWS * CDIM];
__device__ __half g_wqkvh [(size_t)CDIM * QKVCOL];
__device__ __half g_wprojh[(size_t)CDIM * CDIM];
__device__ __half g_qkvh  [(size_t)MROWS * QKVCOL];
__device__ __half g_atth  [(size_t)MROWS * CDIM];
__device__ float  g_bias  [HEADS * 64 * 64];       // padded bias, fp32

// ---------------------------------------------------------------------------
__global__ void f32_to_f16(const float* __restrict__ in, __half* __restrict__ out, int n4)
{
    int i = blockIdx.x * blockDim.x + threadIdx.x;
    if (i < n4) {
        float4 v = ((const float4*)in)[i];
        ((__half2*)out)[2 * i]     = __floats2half2_rn(v.x, v.y);
        ((__half2*)out)[2 * i + 1] = __floats2half2_rn(v.z, v.w);
    }
}

// Precompute padded bias: bias_full[h][i][j].
__global__ void build_bias(const float* __restrict__ bias_table, float* __restrict__ bias_full)
{
    int idx = blockIdx.x * blockDim.x + threadIdx.x;   // 12*64*64 = 49152
    if (idx >= HEADS * 64 * 64) return;
    const int h = idx >> 12;
    const int i = (idx >> 6) & 63;
    const int j = idx & 63;
    float v;
    if (i >= NTOK)       v = 0.0f;
    else if (j >= NTOK)  v = -1.0e4f;
    else {
        const int ri = i / 7, ci = i - ri * 7;
        const int rj = j / 7, cj = j - rj * 7;
        const int rel = (ri - rj + 6) * 13 + (ci - cj + 6);
        v = bias_table[rel * HEADS + h];
    }
    bias_full[idx] = v;
}

// ---------------------------------------------------------------------------
// helpers
// ---------------------------------------------------------------------------
__device__ __forceinline__ void ldsm_x4(unsigned& r0, unsigned& r1, unsigned& r2, unsigned& r3,
                                        const void* p) {
    unsigned a = (unsigned)__cvta_generic_to_shared(p);
    asm volatile("ldmatrix.sync.aligned.m8n8.x4.shared.b16 {%0,%1,%2,%3}, [%4];"
                 : "=r"(r0), "=r"(r1), "=r"(r2), "=r"(r3) : "r"(a));
}
__device__ __forceinline__ void ldsm_x4_t(unsigned& r0, unsigned& r1, unsigned& r2, unsigned& r3,
                                          const void* p) {
    unsigned a = (unsigned)__cvta_generic_to_shared(p);
    asm volatile("ldmatrix.sync.aligned.m8n8.x4.trans.shared.b16 {%0,%1,%2,%3}, [%4];"
                 : "=r"(r0), "=r"(r1), "=r"(r2), "=r"(r3) : "r"(a));
}
__device__ __forceinline__ void cp16(const void* smem_dst, const void* gmem_src) {
    unsigned d = (unsigned)__cvta_generic_to_shared(smem_dst);
    asm volatile("cp.async.cg.shared.global [%0], [%1], 16;" :: "r"(d), "l"(gmem_src));
}
__device__ __forceinline__ void mma_f16(float* d, const unsigned* a, unsigned b0, unsigned b1) {
    asm volatile(
        "mma.sync.aligned.m16n8k16.row.col.f32.f16.f16.f32 "
        "{%0,%1,%2,%3}, {%4,%5,%6,%7}, {%8,%9}, {%0,%1,%2,%3};\n"
        : "+f"(d[0]), "+f"(d[1]), "+f"(d[2]), "+f"(d[3])
        : "r"(a[0]), "r"(a[1]), "r"(a[2]), "r"(a[3]), "r"(b0), "r"(b1));
}
__device__ __forceinline__ unsigned pack2h(float a, float b) {
    __half2 h = __floats2half2_rn(a, b);
    unsigned u;
    memcpy(&u, &h, 4);
    return u;
}

// ---------------------------------------------------------------------------
// FP16 tensor-core GEMM: 128x64 CTA tile, warp tile 32x32 (4Mx2N warps),
// BK=32 halves, 3-stage cp.async, __launch_bounds__(256,3) for 3 CTAs/SM.
// ---------------------------------------------------------------------------
#define BM 128
#define BN 64
#define BKH 32
#define SA 40    // A row stride (80B: conflict-free ldmatrix)
#define SB 72    // B row stride (144B: conflict-free trans ldmatrix)

template<bool OUT_HALF>
__global__ __launch_bounds__(256, 3) void gemm_f16(
    const __half* __restrict__ A, const __half* __restrict__ B,
    const float* __restrict__ bias, void* __restrict__ Cout,
    int M, int N, int K)
{
    __shared__ __align__(16) __half As[3][BM][SA];
    __shared__ __align__(16) __half Bs[3][BKH][SB];

    const int tid  = threadIdx.x;
    const int lane = tid & 31;
    const int warp = tid >> 5;
    const int warpM = warp & 3;     // 0..3
    const int warpN = warp >> 2;    // 0..1
    const int g = lane >> 2;
    const int c = lane & 3;
    const int blockM = blockIdx.y * BM;
    const int blockN = blockIdx.x * BN;

    // cp.async mappings
    const int aRow  = tid >> 2;          // 0..63 (+64)
    const int aCol8 = (tid & 3) * 8;
    const int bRow  = tid >> 3;          // 0..31
    const int bCol8 = (tid & 7) * 8;     // 0..56

    const __half* Aptr0 = A + (long long)(blockM + aRow) * K + aCol8;
    const __half* Aptr1 = A + (long long)(blockM + aRow + 64) * K + aCol8;
    const __half* Bptr  = B + (long long)bRow * N + blockN + bCol8;

    float acc[2][4][4];
#pragma unroll
    for (int mt = 0; mt < 2; mt++)
#pragma unroll
        for (int nt = 0; nt < 4; nt++)
#pragma unroll
            for (int r = 0; r < 4; r++) acc[mt][nt][r] = 0.0f;

    const int nTiles = K / BKH;  // 12

#define ISSUE_STAGE(bufi, kt)                                                      \
    do {                                                                           \
        cp16(&As[bufi][aRow][aCol8],      Aptr0 + (kt) * BKH);                     \
        cp16(&As[bufi][aRow + 64][aCol8], Aptr1 + (kt) * BKH);                     \
        cp16(&Bs[bufi][bRow][bCol8],      Bptr + (long long)(kt) * BKH * N);       \
    } while (0)

    ISSUE_STAGE(0, 0);
    asm volatile("cp.async.commit_group;");
    ISSUE_STAGE(1, 1);
    asm volatile("cp.async.commit_group;");

    int buf = 0;
    for (int kt = 0; kt < nTiles; kt++) {
        asm volatile("cp.async.wait_group 1;");
        __syncthreads();
        if (kt + 2 < nTiles) {
            int nb = buf + 2; if (nb >= 3) nb -= 3;
            ISSUE_STAGE(nb, kt + 2);
        }
        asm volatile("cp.async.commit_group;");

#pragma unroll
        for (int ks = 0; ks < 2; ks++) {
            const int k0 = ks * 16;
            unsigned af[2][4];
#pragma unroll
            for (int mt = 0; mt < 2; mt++) {
                const int r  = warpM * 32 + mt * 16 + (lane & 15);
                const int cc = k0 + (lane >> 4) * 8;
                ldsm_x4(af[mt][0], af[mt][1], af[mt][2], af[mt][3], &As[buf][r][cc]);
            }
            unsigned bf[2][4];
#pragma unroll
            for (int nb2 = 0; nb2 < 2; nb2++) {
                const int rr = k0 + (lane & 15);
                const int cc = warpN * 32 + nb2 * 16 + (lane >> 4) * 8;
                ldsm_x4_t(bf[nb2][0], bf[nb2][1], bf[nb2][2], bf[nb2][3], &Bs[buf][rr][cc]);
            }
#pragma unroll
            for (int mt = 0; mt < 2; mt++)
#pragma unroll
                for (int nt = 0; nt < 4; nt++)
                    mma_f16(acc[mt][nt], af[mt],
                            bf[nt >> 1][(nt & 1) * 2], bf[nt >> 1][(nt & 1) * 2 + 1]);
        }
        buf++; if (buf >= 3) buf = 0;
    }

#pragma unroll
    for (int nt = 0; nt < 4; nt++) {
        const int col = blockN + warpN * 32 + nt * 8 + 2 * c;
        const float bv0 = bias[col];
        const float bv1 = bias[col + 1];
#pragma unroll
        for (int mt = 0; mt < 2; mt++) {
            const long long row0 = blockM + warpM * 32 + mt * 16 + g;
            const float c00 = acc[mt][nt][0] + bv0;
            const float c01 = acc[mt][nt][1] + bv1;
            const float c10 = acc[mt][nt][2] + bv0;
            const float c11 = acc[mt][nt][3] + bv1;
            if (OUT_HALF) {
                __half* C = (__half*)Cout;
                *(__half2*)&C[row0 * N + col]       = __floats2half2_rn(c00, c01);
                *(__half2*)&C[(row0 + 8) * N + col] = __floats2half2_rn(c10, c11);
            } else {
                float* C = (float*)Cout;
                float2 v0 = { c00, c01 };
                float2 v1 = { c10, c11 };
                *(float2*)&C[row0 * N + col]       = v0;
                *(float2*)&C[(row0 + 8) * N + col] = v1;
            }
        }
    }
}

// ---------------------------------------------------------------------------
// Tensor-core window attention (validated R13 version, unchanged)
// ---------------------------------------------------------------------------
#define AST 40

__global__ __launch_bounds__(128) void attn_tc(
    const __half* __restrict__ qkv,
    const float* __restrict__ bias_full,
    __half* __restrict__ out)
{
    __shared__ __align__(16) __half Qs[64][AST];
    __shared__ __align__(16) __half Ks[64][AST];
    __shared__ __align__(16) __half Vs[64][AST];

    const int b    = blockIdx.x;
    const int h    = blockIdx.y;
    const int tid  = threadIdx.x;
    const int wrp  = tid >> 5;
    const int lane = tid & 31;
    const int g    = lane >> 2;
    const int c    = lane & 3;
    const float scale = 0.17677669529663687f;
    const __half2 zero2 = __floats2half2_rn(0.f, 0.f);

    for (int idx = tid; idx < 768; idx += 128) {
        const int t  = idx >> 8;
        const int n  = (idx >> 2) & 63;
        const int ch = idx & 3;
        __half2 v0 = zero2, v1 = zero2, v2 = zero2, v3 = zero2;
        if (n < NTOK) {
            const size_t base = (size_t)(b * NTOK + n) * QKVCOL + t * CDIM + h * HDIM + ch * 8;
            const __half2* p = (const __half2*)&qkv[base];
            v0 = p[0]; v1 = p[1]; v2 = p[2]; v3 = p[3];
            if (t == 0) {
                float2 f;
                f = __half22float2(v0); v0 = __floats2half2_rn(f.x * scale, f.y * scale);
                f = __half22float2(v1); v1 = __floats2half2_rn(f.x * scale, f.y * scale);
                f = __half22float2(v2); v2 = __floats2half2_rn(f.x * scale, f.y * scale);
                f = __half22float2(v3); v3 = __floats2half2_rn(f.x * scale, f.y * scale);
            }
        }
        __half2* dst = (t == 0) ? (__half2*)&Qs[n][ch * 8]
                     : (t == 1) ? (__half2*)&Ks[n][ch * 8]
                                : (__half2*)&Vs[n][ch * 8];
        dst[0] = v0; dst[1] = v1; dst[2] = v2; dst[3] = v3;
    }
    __syncthreads();

    float acc[8][4];
    const float* bh = bias_full + h * 4096;
#pragma unroll
    for (int nt = 0; nt < 8; nt++) {
        const float2 b0 = *(const float2*)&bh[(16 * wrp + g) * 64 + 8 * nt + 2 * c];
        const float2 b1 = *(const float2*)&bh[(16 * wrp + 8 + g) * 64 + 8 * nt + 2 * c];
        acc[nt][0] = b0.x; acc[nt][1] = b0.y;
        acc[nt][2] = b1.x; acc[nt][3] = b1.y;
    }

#pragma unroll
    for (int kt = 0; kt < 2; kt++) {
        const int k0 = kt * 16;
        unsigned af[4];
        ldsm_x4(af[0], af[1], af[2], af[3],
                &Qs[16 * wrp + (lane & 15)][k0 + (lane >> 4) * 8]);
        unsigned bf[4][4];
#pragma unroll
        for (int ntg = 0; ntg < 4; ntg++) {
            const int rr = 16 * ntg + (lane & 7) + ((lane >> 4) & 1) * 8;
            const int cc = k0 + ((lane >> 3) & 1) * 8;
            ldsm_x4(bf[ntg][0], bf[ntg][1], bf[ntg][2], bf[ntg][3], &Ks[rr][cc]);
        }
#pragma unroll
        for (int nt = 0; nt < 8; nt++)
            mma_f16(acc[nt], af,
                    bf[nt >> 1][(nt & 1) * 2], bf[nt >> 1][(nt & 1) * 2 + 1]);
    }

    float inv[2];
#pragma unroll
    for (int rh = 0; rh < 2; rh++) {
        float m = -1e30f;
#pragma unroll
        for (int nt = 0; nt < 8; nt++) {
            m = fmaxf(m, acc[nt][2 * rh]);
            m = fmaxf(m, acc[nt][2 * rh + 1]);
        }
        m = fmaxf(m, __shfl_xor_sync(0xffffffffu, m, 1));
        m = fmaxf(m, __shfl_xor_sync(0xffffffffu, m, 2));
        float s = 0.0f;
#pragma unroll
        for (int nt = 0; nt < 8; nt++) {
            const float e0 = __expf(acc[nt][2 * rh]     - m);
            const float e1 = __expf(acc[nt][2 * rh + 1] - m);
            acc[nt][2 * rh]     = e0;
            acc[nt][2 * rh + 1] = e1;
            s += e0 + e1;
        }
        s += __shfl_xor_sync(0xffffffffu, s, 1);
        s += __shfl_xor_sync(0xffffffffu, s, 2);
        inv[rh] = __fdividef(1.0f, s);
    }

    unsigned pa[4][4];
#pragma unroll
    for (int kt = 0; kt < 4; kt++) {
        pa[kt][0] = pack2h(acc[2 * kt][0],     acc[2 * kt][1]);
        pa[kt][1] = pack2h(acc[2 * kt][2],     acc[2 * kt][3]);
        pa[kt][2] = pack2h(acc[2 * kt + 1][0], acc[2 * kt + 1][1]);
        pa[kt][3] = pack2h(acc[2 * kt + 1][2], acc[2 * kt + 1][3]);
    }

    float oacc[4][4];
#pragma unroll
    for (int nt = 0; nt < 4; nt++)
#pragma unroll
        for (int r = 0; r < 4; r++) oacc[nt][r] = 0.0f;

#pragma unroll
    for (int kt = 0; kt < 4; kt++) {
        unsigned bv[2][4];
#pragma unroll
        for (int ntg = 0; ntg < 2; ntg++) {
            const int rr = 16 * kt + (lane & 15);
            const int cc = 16 * ntg + (lane >> 4) * 8;
            ldsm_x4_t(bv[ntg][0], bv[ntg][1], bv[ntg][2], bv[ntg][3], &Vs[rr][cc]);
        }
#pragma unroll
        for (int nt = 0; nt < 4; nt++)
            mma_f16(oacc[nt], pa[kt],
                    bv[nt >> 1][(nt & 1) * 2], bv[nt >> 1][(nt & 1) * 2 + 1]);
    }

    const int i0 = 16 * wrp + g;
    const int i1 = i0 + 8;
#pragma unroll
    for (int nt = 0; nt < 4; nt++) {
        const int col = 8 * nt + 2 * c;
        if (i0 < NTOK) {
            *(__half2*)&out[(size_t)(b * NTOK + i0) * CDIM + h * HDIM + col] =
                __floats2half2_rn(oacc[nt][0] * inv[0], oacc[nt][1] * inv[0]);
        }
        if (i1 < NTOK) {
            *(__half2*)&out[(size_t)(b * NTOK + i1) * CDIM + h * HDIM + col] =
                __floats2half2_rn(oacc[nt][2] * inv[1], oacc[nt][3] * inv[1]);
        }
    }
}

// ---------------------------------------------------------------------------
extern "C" void kernel_launch(void* const* d_in, const int* in_sizes, int n_in,
                              void* d_out, int out_size)
{
    const float* x          = (const float*)d_in[0];
    const float* w_qkv      = (const float*)d_in[1];
    const float* b_qkv      = (const float*)d_in[2];
    const float* w_proj     = (const float*)d_in[3];
    const float* b_proj     = (const float*)d_in[4];
    const float* bias_table = (const float*)d_in[5];
    float* out = (float*)d_out;

    __half *xh, *wqkvh, *wprojh, *qkvh, *atth;
    float* biasf;
    cudaGetSymbolAddress((void**)&xh,     g_xh);
    cudaGetSymbolAddress((void**)&wqkvh,  g_wqkvh);
    cudaGetSymbolAddress((void**)&wprojh, g_wprojh);
    cudaGetSymbolAddress((void**)&qkvh,   g_qkvh);
    cudaGetSymbolAddress((void**)&atth,   g_atth);
    cudaGetSymbolAddress((void**)&biasf,  g_bias);

    // 0) conversions + bias build
    {
        const int n4x = MROWS * CDIM / 4;
        f32_to_f16<<<(n4x + 255) / 256, 256>>>(x, xh, n4x);
        const int n4q = CDIM * QKVCOL / 4;
        f32_to_f16<<<(n4q + 255) / 256, 256>>>(w_qkv, wqkvh, n4q);
        const int n4p = CDIM * CDIM / 4;
        f32_to_f16<<<(n4p + 255) / 256, 256>>>(w_proj, wprojh, n4p);
        build_bias<<<(HEADS * 64 * 64 + 1023) / 1024, 1024>>>(bias_table, biasf);
    }
    // 1) QKV = x @ w_qkv + b_qkv (fp16 out)
    {
        dim3 grid(QKVCOL / BN, MROWS / BM);   // (18, 1568)
        gemm_f16<true><<<grid, 256>>>(xh, wqkvh, b_qkv, qkvh, MROWS, QKVCOL, CDIM);
    }
    // 2) Tensor-core windowed attention (fp16 in/out)
    {
        dim3 grid(NWIN, HEADS);
        attn_tc<<<grid, 128>>>(qkvh, biasf, atth);
    }
    // 3) out = att @ w_proj + b_proj (fp32 out)
    {
        dim3 grid(CDIM / BN, MROWS / BM);     // (6, 1568)
        gemm_f16<false><<<grid, 256>>>(atth, wprojh, b_proj, out, MROWS, CDIM, CDIM);
    }
}

// round 16
// speedup vs baseline: 1.1258x; 1.1258x over previous
#include <cuda_runtime.h>
#include <cuda_fp16.h>
#include <float.h>
#include <string.h>

// Problem constants
#define NWIN   4096
#define NTOK   49
#define CDIM   384
#define HEADS  12
#define HDIM   32
#define MROWS  (NWIN * NTOK)        // 200704
#define QKVCOL (3 * CDIM)           // 1152

// Scratch (allocation-free rule: __device__ globals)
__device__ __half g_xh    [(size_t)MROWS * CDIM];
__device__ __half g_wqkvh [(size_t)CDIM * QKVCOL];
__device__ __half g_wprojh[(size_t)CDIM * CDIM];
__device__ __half g_qkvh  [(size_t)MROWS * QKVCOL];
__device__ __half g_atth  [(size_t)MROWS * CDIM];
__device__ float  g_bias  [HEADS * 64 * 64];       // padded bias, fp32

// ---------------------------------------------------------------------------
__global__ void f32_to_f16(const float* __restrict__ in, __half* __restrict__ out, int n4)
{
    int i = blockIdx.x * blockDim.x + threadIdx.x;
    if (i < n4) {
        float4 v = ((const float4*)in)[i];
        ((__half2*)out)[2 * i]     = __floats2half2_rn(v.x, v.y);
        ((__half2*)out)[2 * i + 1] = __floats2half2_rn(v.z, v.w);
    }
}

// Precompute padded bias: bias_full[h][i][j].
__global__ void build_bias(const float* __restrict__ bias_table, float* __restrict__ bias_full)
{
    int idx = blockIdx.x * blockDim.x + threadIdx.x;   // 12*64*64 = 49152
    if (idx >= HEADS * 64 * 64) return;
    const int h = idx >> 12;
    const int i = (idx >> 6) & 63;
    const int j = idx & 63;
    float v;
    if (i >= NTOK)       v = 0.0f;
    else if (j >= NTOK)  v = -1.0e4f;
    else {
        const int ri = i / 7, ci = i - ri * 7;
        const int rj = j / 7, cj = j - rj * 7;
        const int rel = (ri - rj + 6) * 13 + (ci - cj + 6);
        v = bias_table[rel * HEADS + h];
    }
    bias_full[idx] = v;
}

// ---------------------------------------------------------------------------
// helpers
// ---------------------------------------------------------------------------
__device__ __forceinline__ void ldsm_x4(unsigned& r0, unsigned& r1, unsigned& r2, unsigned& r3,
                                        const void* p) {
    unsigned a = (unsigned)__cvta_generic_to_shared(p);
    asm volatile("ldmatrix.sync.aligned.m8n8.x4.shared.b16 {%0,%1,%2,%3}, [%4];"
                 : "=r"(r0), "=r"(r1), "=r"(r2), "=r"(r3) : "r"(a));
}
__device__ __forceinline__ void ldsm_x4_t(unsigned& r0, unsigned& r1, unsigned& r2, unsigned& r3,
                                          const void* p) {
    unsigned a = (unsigned)__cvta_generic_to_shared(p);
    asm volatile("ldmatrix.sync.aligned.m8n8.x4.trans.shared.b16 {%0,%1,%2,%3}, [%4];"
                 : "=r"(r0), "=r"(r1), "=r"(r2), "=r"(r3) : "r"(a));
}
__device__ __forceinline__ void cp16(const void* smem_dst, const void* gmem_src) {
    unsigned d = (unsigned)__cvta_generic_to_shared(smem_dst);
    asm volatile("cp.async.cg.shared.global [%0], [%1], 16;" :: "r"(d), "l"(gmem_src));
}
__device__ __forceinline__ void mma_f16(float* d, const unsigned* a, unsigned b0, unsigned b1) {
    asm volatile(
        "mma.sync.aligned.m16n8k16.row.col.f32.f16.f16.f32 "
        "{%0,%1,%2,%3}, {%4,%5,%6,%7}, {%8,%9}, {%0,%1,%2,%3};\n"
        : "+f"(d[0]), "+f"(d[1]), "+f"(d[2]), "+f"(d[3])
        : "r"(a[0]), "r"(a[1]), "r"(a[2]), "r"(a[3]), "r"(b0), "r"(b1));
}
__device__ __forceinline__ unsigned pack2h(float a, float b) {
    __half2 h = __floats2half2_rn(a, b);
    unsigned u;
    memcpy(&u, &h, 4);
    return u;
}

// ---------------------------------------------------------------------------
// FP16 tensor-core GEMM: 128x128 CTA tile, warp tile 32x64 (R13 shape),
// BK=64 halves (6 iterations, half the barriers of R13), 3-stage cp.async,
// dynamic smem (105 KB, 2 CTAs/SM).
// ---------------------------------------------------------------------------
#define BM 128
#define BN 128
#define BKH 64
#define A_ROWB 144               // A row stride bytes (72 halves: conflict-free)
#define B_ROWB 272               // B row stride bytes (136 halves: conflict-free)
#define A_STAGE (128 * A_ROWB)   // 18432
#define B_STAGE (64 * B_ROWB)    // 17408
#define GSMEM   (3 * (A_STAGE + B_STAGE))   // 107520

template<bool OUT_HALF>
__global__ __launch_bounds__(256) void gemm_f16(
    const __half* __restrict__ A, const __half* __restrict__ B,
    const float* __restrict__ bias, void* __restrict__ Cout,
    int M, int N, int K)
{
    extern __shared__ __align__(16) char smem[];
    char* const Abase = smem;
    char* const Bbase = smem + 3 * A_STAGE;

    const int tid  = threadIdx.x;
    const int lane = tid & 31;
    const int warp = tid >> 5;
    const int warpM = warp & 3;     // 0..3
    const int warpN = warp >> 2;    // 0..1
    const int g = lane >> 2;
    const int c = lane & 3;
    const int blockM = blockIdx.y * BM;
    const int blockN = blockIdx.x * BN;

    // loaders: A tile 128x64 halves (8 chunks/row), B tile 64x128 halves (16 chunks/row)
    const int aRow0 = tid >> 3;      // 0..31 (+32i)
    const int aCh   = tid & 7;
    const int bRow0 = tid >> 4;      // 0..15 (+16i)
    const int bCh   = tid & 15;

    float acc[2][8][4];
#pragma unroll
    for (int mt = 0; mt < 2; mt++)
#pragma unroll
        for (int nt = 0; nt < 8; nt++)
#pragma unroll
            for (int r = 0; r < 4; r++) acc[mt][nt][r] = 0.0f;

    const int nTiles = K / BKH;  // 6

#define ISSUE_STAGE(bufi, kt)                                                          \
    do {                                                                               \
        _Pragma("unroll")                                                              \
        for (int i = 0; i < 4; i++) {                                                  \
            const int rA = aRow0 + 32 * i;                                             \
            cp16(Abase + (bufi) * A_STAGE + rA * A_ROWB + aCh * 16,                    \
                 A + (size_t)(blockM + rA) * K + (size_t)(kt) * BKH + aCh * 8);        \
        }                                                                              \
        _Pragma("unroll")                                                              \
        for (int i = 0; i < 4; i++) {                                                  \
            const int rB = bRow0 + 16 * i;                                             \
            cp16(Bbase + (bufi) * B_STAGE + rB * B_ROWB + bCh * 16,                    \
                 B + (size_t)((kt) * BKH + rB) * N + blockN + bCh * 8);                \
        }                                                                              \
    } while (0)

    ISSUE_STAGE(0, 0);
    asm volatile("cp.async.commit_group;");
    ISSUE_STAGE(1, 1);
    asm volatile("cp.async.commit_group;");

    int buf = 0;
    for (int kt = 0; kt < nTiles; kt++) {
        asm volatile("cp.async.wait_group 1;");
        __syncthreads();
        if (kt + 2 < nTiles) {
            int nb = buf + 2; if (nb >= 3) nb -= 3;
            ISSUE_STAGE(nb, kt + 2);
        }
        asm volatile("cp.async.commit_group;");

        const char* Abuf = Abase + buf * A_STAGE;
        const char* Bbuf = Bbase + buf * B_STAGE;
#pragma unroll
        for (int ks = 0; ks < 4; ks++) {
            const int k0 = ks * 16;
            unsigned af[2][4];
#pragma unroll
            for (int mt = 0; mt < 2; mt++) {
                const int r  = warpM * 32 + mt * 16 + (lane & 15);
                const int cc = k0 + (lane >> 4) * 8;
                ldsm_x4(af[mt][0], af[mt][1], af[mt][2], af[mt][3],
                        Abuf + r * A_ROWB + cc * 2);
            }
            unsigned bf[4][4];
#pragma unroll
            for (int nb2 = 0; nb2 < 4; nb2++) {
                const int rr = k0 + (lane & 15);
                const int cc = warpN * 64 + nb2 * 16 + (lane >> 4) * 8;
                ldsm_x4_t(bf[nb2][0], bf[nb2][1], bf[nb2][2], bf[nb2][3],
                          Bbuf + rr * B_ROWB + cc * 2);
            }
#pragma unroll
            for (int mt = 0; mt < 2; mt++)
#pragma unroll
                for (int nt = 0; nt < 8; nt++)
                    mma_f16(acc[mt][nt], af[mt],
                            bf[nt >> 1][(nt & 1) * 2], bf[nt >> 1][(nt & 1) * 2 + 1]);
        }
        buf++; if (buf >= 3) buf = 0;
    }

#pragma unroll
    for (int nt = 0; nt < 8; nt++) {
        const int col = blockN + warpN * 64 + nt * 8 + 2 * c;
        const float bv0 = bias[col];
        const float bv1 = bias[col + 1];
#pragma unroll
        for (int mt = 0; mt < 2; mt++) {
            const long long row0 = blockM + warpM * 32 + mt * 16 + g;
            const float c00 = acc[mt][nt][0] + bv0;
            const float c01 = acc[mt][nt][1] + bv1;
            const float c10 = acc[mt][nt][2] + bv0;
            const float c11 = acc[mt][nt][3] + bv1;
            if (OUT_HALF) {
                __half* C = (__half*)Cout;
                *(__half2*)&C[row0 * N + col]       = __floats2half2_rn(c00, c01);
                *(__half2*)&C[(row0 + 8) * N + col] = __floats2half2_rn(c10, c11);
            } else {
                float* C = (float*)Cout;
                float2 v0 = { c00, c01 };
                float2 v1 = { c10, c11 };
                *(float2*)&C[row0 * N + col]       = v0;
                *(float2*)&C[(row0 + 8) * N + col] = v1;
            }
        }
    }
}

// ---------------------------------------------------------------------------
// Tensor-core window attention (validated R13 version, unchanged)
// ---------------------------------------------------------------------------
#define AST 40

__global__ __launch_bounds__(128) void attn_tc(
    const __half* __restrict__ qkv,
    const float* __restrict__ bias_full,
    __half* __restrict__ out)
{
    __shared__ __align__(16) __half Qs[64][AST];
    __shared__ __align__(16) __half Ks[64][AST];
    __shared__ __align__(16) __half Vs[64][AST];

    const int b    = blockIdx.x;
    const int h    = blockIdx.y;
    const int tid  = threadIdx.x;
    const int wrp  = tid >> 5;
    const int lane = tid & 31;
    const int g    = lane >> 2;
    const int c    = lane & 3;
    const float scale = 0.17677669529663687f;
    const __half2 zero2 = __floats2half2_rn(0.f, 0.f);

    for (int idx = tid; idx < 768; idx += 128) {
        const int t  = idx >> 8;
        const int n  = (idx >> 2) & 63;
        const int ch = idx & 3;
        __half2 v0 = zero2, v1 = zero2, v2 = zero2, v3 = zero2;
        if (n < NTOK) {
            const size_t base = (size_t)(b * NTOK + n) * QKVCOL + t * CDIM + h * HDIM + ch * 8;
            const __half2* p = (const __half2*)&qkv[base];
            v0 = p[0]; v1 = p[1]; v2 = p[2]; v3 = p[3];
            if (t == 0) {
                float2 f;
                f = __half22float2(v0); v0 = __floats2half2_rn(f.x * scale, f.y * scale);
                f = __half22float2(v1); v1 = __floats2half2_rn(f.x * scale, f.y * scale);
                f = __half22float2(v2); v2 = __floats2half2_rn(f.x * scale, f.y * scale);
                f = __half22float2(v3); v3 = __floats2half2_rn(f.x * scale, f.y * scale);
            }
        }
        __half2* dst = (t == 0) ? (__half2*)&Qs[n][ch * 8]
                     : (t == 1) ? (__half2*)&Ks[n][ch * 8]
                                : (__half2*)&Vs[n][ch * 8];
        dst[0] = v0; dst[1] = v1; dst[2] = v2; dst[3] = v3;
    }
    __syncthreads();

    float acc[8][4];
    const float* bh = bias_full + h * 4096;
#pragma unroll
    for (int nt = 0; nt < 8; nt++) {
        const float2 b0 = *(const float2*)&bh[(16 * wrp + g) * 64 + 8 * nt + 2 * c];
        const float2 b1 = *(const float2*)&bh[(16 * wrp + 8 + g) * 64 + 8 * nt + 2 * c];
        acc[nt][0] = b0.x; acc[nt][1] = b0.y;
        acc[nt][2] = b1.x; acc[nt][3] = b1.y;
    }

#pragma unroll
    for (int kt = 0; kt < 2; kt++) {
        const int k0 = kt * 16;
        unsigned af[4];
        ldsm_x4(af[0], af[1], af[2], af[3],
                &Qs[16 * wrp + (lane & 15)][k0 + (lane >> 4) * 8]);
        unsigned bf[4][4];
#pragma unroll
        for (int ntg = 0; ntg < 4; ntg++) {
            const int rr = 16 * ntg + (lane & 7) + ((lane >> 4) & 1) * 8;
            const int cc = k0 + ((lane >> 3) & 1) * 8;
            ldsm_x4(bf[ntg][0], bf[ntg][1], bf[ntg][2], bf[ntg][3], &Ks[rr][cc]);
        }
#pragma unroll
        for (int nt = 0; nt < 8; nt++)
            mma_f16(acc[nt], af,
                    bf[nt >> 1][(nt & 1) * 2], bf[nt >> 1][(nt & 1) * 2 + 1]);
    }

    float inv[2];
#pragma unroll
    for (int rh = 0; rh < 2; rh++) {
        float m = -1e30f;
#pragma unroll
        for (int nt = 0; nt < 8; nt++) {
            m = fmaxf(m, acc[nt][2 * rh]);
            m = fmaxf(m, acc[nt][2 * rh + 1]);
        }
        m = fmaxf(m, __shfl_xor_sync(0xffffffffu, m, 1));
        m = fmaxf(m, __shfl_xor_sync(0xffffffffu, m, 2));
        float s = 0.0f;
#pragma unroll
        for (int nt = 0; nt < 8; nt++) {
            const float e0 = __expf(acc[nt][2 * rh]     - m);
            const float e1 = __expf(acc[nt][2 * rh + 1] - m);
            acc[nt][2 * rh]     = e0;
            acc[nt][2 * rh + 1] = e1;
            s += e0 + e1;
        }
        s += __shfl_xor_sync(0xffffffffu, s, 1);
        s += __shfl_xor_sync(0xffffffffu, s, 2);
        inv[rh] = __fdividef(1.0f, s);
    }

    unsigned pa[4][4];
#pragma unroll
    for (int kt = 0; kt < 4; kt++) {
        pa[kt][0] = pack2h(acc[2 * kt][0],     acc[2 * kt][1]);
        pa[kt][1] = pack2h(acc[2 * kt][2],     acc[2 * kt][3]);
        pa[kt][2] = pack2h(acc[2 * kt + 1][0], acc[2 * kt + 1][1]);
        pa[kt][3] = pack2h(acc[2 * kt + 1][2], acc[2 * kt + 1][3]);
    }

    float oacc[4][4];
#pragma unroll
    for (int nt = 0; nt < 4; nt++)
#pragma unroll
        for (int r = 0; r < 4; r++) oacc[nt][r] = 0.0f;

#pragma unroll
    for (int kt = 0; kt < 4; kt++) {
        unsigned bv[2][4];
#pragma unroll
        for (int ntg = 0; ntg < 2; ntg++) {
            const int rr = 16 * kt + (lane & 15);
            const int cc = 16 * ntg + (lane >> 4) * 8;
            ldsm_x4_t(bv[ntg][0], bv[ntg][1], bv[ntg][2], bv[ntg][3], &Vs[rr][cc]);
        }
#pragma unroll
        for (int nt = 0; nt < 4; nt++)
            mma_f16(oacc[nt], pa[kt],
                    bv[nt >> 1][(nt & 1) * 2], bv[nt >> 1][(nt & 1) * 2 + 1]);
    }

    const int i0 = 16 * wrp + g;
    const int i1 = i0 + 8;
#pragma unroll
    for (int nt = 0; nt < 4; nt++) {
        const int col = 8 * nt + 2 * c;
        if (i0 < NTOK) {
            *(__half2*)&out[(size_t)(b * NTOK + i0) * CDIM + h * HDIM + col] =
                __floats2half2_rn(oacc[nt][0] * inv[0], oacc[nt][1] * inv[0]);
        }
        if (i1 < NTOK) {
            *(__half2*)&out[(size_t)(b * NTOK + i1) * CDIM + h * HDIM + col] =
                __floats2half2_rn(oacc[nt][2] * inv[1], oacc[nt][3] * inv[1]);
        }
    }
}

// ---------------------------------------------------------------------------
extern "C" void kernel_launch(void* const* d_in, const int* in_sizes, int n_in,
                              void* d_out, int out_size)
{
    const float* x          = (const float*)d_in[0];
    const float* w_qkv      = (const float*)d_in[1];
    const float* b_qkv      = (const float*)d_in[2];
    const float* w_proj     = (const float*)d_in[3];
    const float* b_proj     = (const float*)d_in[4];
    const float* bias_table = (const float*)d_in[5];
    float* out = (float*)d_out;

    __half *xh, *wqkvh, *wprojh, *qkvh, *atth;
    float* biasf;
    cudaGetSymbolAddress((void**)&xh,     g_xh);
    cudaGetSymbolAddress((void**)&wqkvh,  g_wqkvh);
    cudaGetSymbolAddress((void**)&wprojh, g_wprojh);
    cudaGetSymbolAddress((void**)&qkvh,   g_qkvh);
    cudaGetSymbolAddress((void**)&atth,   g_atth);
    cudaGetSymbolAddress((void**)&biasf,  g_bias);

    // Allow 105 KB dynamic smem (idempotent; host-side API, capture-safe)
    cudaFuncSetAttribute(gemm_f16<true>,  cudaFuncAttributeMaxDynamicSharedMemorySize, GSMEM);
    cudaFuncSetAttribute(gemm_f16<false>, cudaFuncAttributeMaxDynamicSharedMemorySize, GSMEM);

    // 0) conversions + bias build
    {
        const int n4x = MROWS * CDIM / 4;
        f32_to_f16<<<(n4x + 255) / 256, 256>>>(x, xh, n4x);
        const int n4q = CDIM * QKVCOL / 4;
        f32_to_f16<<<(n4q + 255) / 256, 256>>>(w_qkv, wqkvh, n4q);
        const int n4p = CDIM * CDIM / 4;
        f32_to_f16<<<(n4p + 255) / 256, 256>>>(w_proj, wprojh, n4p);
        build_bias<<<(HEADS * 64 * 64 + 1023) / 1024, 1024>>>(bias_table, biasf);
    }
    // 1) QKV = x @ w_qkv + b_qkv (fp16 out)
    {
        dim3 grid(QKVCOL / BN, MROWS / BM);   // (9, 1568)
        gemm_f16<true><<<grid, 256, GSMEM>>>(xh, wqkvh, b_qkv, qkvh, MROWS, QKVCOL, CDIM);
    }
    // 2) Tensor-core windowed attention (fp16 in/out)
    {
        dim3 grid(NWIN, HEADS);
        attn_tc<<<grid, 128>>>(qkvh, biasf, atth);
    }
    // 3) out = att @ w_proj + b_proj (fp32 out)
    {
        dim3 grid(CDIM / BN, MROWS / BM);     // (3, 1568)
        gemm_f16<false><<<grid, 256, GSMEM>>>(atth, wprojh, b_proj, out, MROWS, CDIM, CDIM);
    }
}

// round 17
// speedup vs baseline: 1.3180x; 1.1707x over previous
#include <cuda_runtime.h>
#include <cuda_fp16.h>
#include <float.h>
#include <string.h>

// Problem constants
#define NWIN   4096
#define NTOK   49
#define CDIM   384
#define HEADS  12
#define HDIM   32
#define MROWS  (NWIN * NTOK)        // 200704
#define QKVCOL (3 * CDIM)           // 1152

// Scratch (allocation-free rule: __device__ globals)
__device__ __half g_xh    [(size_t)MROWS * CDIM];
__device__ __half g_wqkvh [(size_t)CDIM * QKVCOL];
__device__ __half g_wprojh[(size_t)CDIM * CDIM];
__device__ __half g_qkvh  [(size_t)MROWS * QKVCOL];
__device__ __half g_atth  [(size_t)MROWS * CDIM];
__device__ float  g_bias  [HEADS * 64 * 64];       // padded bias / scale, fp32

// ---------------------------------------------------------------------------
__global__ void f32_to_f16(const float* __restrict__ in, __half* __restrict__ out, int n4)
{
    int i = blockIdx.x * blockDim.x + threadIdx.x;
    if (i < n4) {
        float4 v = ((const float4*)in)[i];
        ((__half2*)out)[2 * i]     = __floats2half2_rn(v.x, v.y);
        ((__half2*)out)[2 * i + 1] = __floats2half2_rn(v.z, v.w);
    }
}

// Precompute padded bias, PRE-DIVIDED BY SCALE (softmax folds scale back in):
// stored = S_true / scale.  i>=49: 0; j>=49: -1e4/scale (masks pad cols).
#define ATT_SCALE 0.17677669529663687f
__global__ void build_bias(const float* __restrict__ bias_table, float* __restrict__ bias_full)
{
    int idx = blockIdx.x * blockDim.x + threadIdx.x;   // 12*64*64 = 49152
    if (idx >= HEADS * 64 * 64) return;
    const int h = idx >> 12;
    const int i = (idx >> 6) & 63;
    const int j = idx & 63;
    float v;
    if (i >= NTOK)       v = 0.0f;
    else if (j >= NTOK)  v = -1.0e4f / ATT_SCALE;
    else {
        const int ri = i / 7, ci = i - ri * 7;
        const int rj = j / 7, cj = j - rj * 7;
        const int rel = (ri - rj + 6) * 13 + (ci - cj + 6);
        v = bias_table[rel * HEADS + h] / ATT_SCALE;
    }
    bias_full[idx] = v;
}

// ---------------------------------------------------------------------------
// helpers
// ---------------------------------------------------------------------------
__device__ __forceinline__ void ldsm_x4(unsigned& r0, unsigned& r1, unsigned& r2, unsigned& r3,
                                        const void* p) {
    unsigned a = (unsigned)__cvta_generic_to_shared(p);
    asm volatile("ldmatrix.sync.aligned.m8n8.x4.shared.b16 {%0,%1,%2,%3}, [%4];"
                 : "=r"(r0), "=r"(r1), "=r"(r2), "=r"(r3) : "r"(a));
}
__device__ __forceinline__ void ldsm_x4_t(unsigned& r0, unsigned& r1, unsigned& r2, unsigned& r3,
                                          const void* p) {
    unsigned a = (unsigned)__cvta_generic_to_shared(p);
    asm volatile("ldmatrix.sync.aligned.m8n8.x4.trans.shared.b16 {%0,%1,%2,%3}, [%4];"
                 : "=r"(r0), "=r"(r1), "=r"(r2), "=r"(r3) : "r"(a));
}
__device__ __forceinline__ void cp16(const void* smem_dst, const void* gmem_src) {
    unsigned d = (unsigned)__cvta_generic_to_shared(smem_dst);
    asm volatile("cp.async.cg.shared.global [%0], [%1], 16;" :: "r"(d), "l"(gmem_src));
}
__device__ __forceinline__ void mma_f16(float* d, const unsigned* a, unsigned b0, unsigned b1) {
    asm volatile(
        "mma.sync.aligned.m16n8k16.row.col.f32.f16.f16.f32 "
        "{%0,%1,%2,%3}, {%4,%5,%6,%7}, {%8,%9}, {%0,%1,%2,%3};\n"
        : "+f"(d[0]), "+f"(d[1]), "+f"(d[2]), "+f"(d[3])
        : "r"(a[0]), "r"(a[1]), "r"(a[2]), "r"(a[3]), "r"(b0), "r"(b1));
}
__device__ __forceinline__ unsigned pack2h(float a, float b) {
    __half2 h = __floats2half2_rn(a, b);
    unsigned u;
    memcpy(&u, &h, 4);
    return u;
}

// ---------------------------------------------------------------------------
// FP16 tensor-core GEMM (R16-validated: 128x128, warp 32x64, BK=64, 3 stages)
// ---------------------------------------------------------------------------
#define BM 128
#define BN 128
#define BKH 64
#define A_ROWB 144
#define B_ROWB 272
#define A_STAGE (128 * A_ROWB)
#define B_STAGE (64 * B_ROWB)
#define GSMEM   (3 * (A_STAGE + B_STAGE))   // 107520

template<bool OUT_HALF>
__global__ __launch_bounds__(256) void gemm_f16(
    const __half* __restrict__ A, const __half* __restrict__ B,
    const float* __restrict__ bias, void* __restrict__ Cout,
    int M, int N, int K)
{
    extern __shared__ __align__(16) char smem[];
    char* const Abase = smem;
    char* const Bbase = smem + 3 * A_STAGE;

    const int tid  = threadIdx.x;
    const int lane = tid & 31;
    const int warp = tid >> 5;
    const int warpM = warp & 3;
    const int warpN = warp >> 2;
    const int g = lane >> 2;
    const int c = lane & 3;
    const int blockM = blockIdx.y * BM;
    const int blockN = blockIdx.x * BN;

    const int aRow0 = tid >> 3;
    const int aCh   = tid & 7;
    const int bRow0 = tid >> 4;
    const int bCh   = tid & 15;

    float acc[2][8][4];
#pragma unroll
    for (int mt = 0; mt < 2; mt++)
#pragma unroll
        for (int nt = 0; nt < 8; nt++)
#pragma unroll
            for (int r = 0; r < 4; r++) acc[mt][nt][r] = 0.0f;

    const int nTiles = K / BKH;

#define ISSUE_STAGE(bufi, kt)                                                          \
    do {                                                                               \
        _Pragma("unroll")                                                              \
        for (int i = 0; i < 4; i++) {                                                  \
            const int rA = aRow0 + 32 * i;                                             \
            cp16(Abase + (bufi) * A_STAGE + rA * A_ROWB + aCh * 16,                    \
                 A + (size_t)(blockM + rA) * K + (size_t)(kt) * BKH + aCh * 8);        \
        }                                                                              \
        _Pragma("unroll")                                                              \
        for (int i = 0; i < 4; i++) {                                                  \
            const int rB = bRow0 + 16 * i;                                             \
            cp16(Bbase + (bufi) * B_STAGE + rB * B_ROWB + bCh * 16,                    \
                 B + (size_t)((kt) * BKH + rB) * N + blockN + bCh * 8);                \
        }                                                                              \
    } while (0)

    ISSUE_STAGE(0, 0);
    asm volatile("cp.async.commit_group;");
    ISSUE_STAGE(1, 1);
    asm volatile("cp.async.commit_group;");

    int buf = 0;
    for (int kt = 0; kt < nTiles; kt++) {
        asm volatile("cp.async.wait_group 1;");
        __syncthreads();
        if (kt + 2 < nTiles) {
            int nb = buf + 2; if (nb >= 3) nb -= 3;
            ISSUE_STAGE(nb, kt + 2);
        }
        asm volatile("cp.async.commit_group;");

        const char* Abuf = Abase + buf * A_STAGE;
        const char* Bbuf = Bbase + buf * B_STAGE;
#pragma unroll
        for (int ks = 0; ks < 4; ks++) {
            const int k0 = ks * 16;
            unsigned af[2][4];
#pragma unroll
            for (int mt = 0; mt < 2; mt++) {
                const int r  = warpM * 32 + mt * 16 + (lane & 15);
                const int cc = k0 + (lane >> 4) * 8;
                ldsm_x4(af[mt][0], af[mt][1], af[mt][2], af[mt][3],
                        Abuf + r * A_ROWB + cc * 2);
            }
            unsigned bf[4][4];
#pragma unroll
            for (int nb2 = 0; nb2 < 4; nb2++) {
                const int rr = k0 + (lane & 15);
                const int cc = warpN * 64 + nb2 * 16 + (lane >> 4) * 8;
                ldsm_x4_t(bf[nb2][0], bf[nb2][1], bf[nb2][2], bf[nb2][3],
                          Bbuf + rr * B_ROWB + cc * 2);
            }
#pragma unroll
            for (int mt = 0; mt < 2; mt++)
#pragma unroll
                for (int nt = 0; nt < 8; nt++)
                    mma_f16(acc[mt][nt], af[mt],
                            bf[nt >> 1][(nt & 1) * 2], bf[nt >> 1][(nt & 1) * 2 + 1]);
        }
        buf++; if (buf >= 3) buf = 0;
    }

#pragma unroll
    for (int nt = 0; nt < 8; nt++) {
        const int col = blockN + warpN * 64 + nt * 8 + 2 * c;
        const float bv0 = bias[col];
        const float bv1 = bias[col + 1];
#pragma unroll
        for (int mt = 0; mt < 2; mt++) {
            const long long row0 = blockM + warpM * 32 + mt * 16 + g;
            const float c00 = acc[mt][nt][0] + bv0;
            const float c01 = acc[mt][nt][1] + bv1;
            const float c10 = acc[mt][nt][2] + bv0;
            const float c11 = acc[mt][nt][3] + bv1;
            if (OUT_HALF) {
                __half* C = (__half*)Cout;
                *(__half2*)&C[row0 * N + col]       = __floats2half2_rn(c00, c01);
                *(__half2*)&C[(row0 + 8) * N + col] = __floats2half2_rn(c10, c11);
            } else {
                float* C = (float*)Cout;
                float2 v0 = { c00, c01 };
                float2 v1 = { c10, c11 };
                *(float2*)&C[row0 * N + col]       = v0;
                *(float2*)&C[(row0 + 8) * N + col] = v1;
            }
        }
    }
}

// ---------------------------------------------------------------------------
// Attention v3: block = (8-window group, head), 128 threads (4 warps).
// Q/K/V staged raw via cp.async, 3-stage pipeline across windows (GEMM
// skeleton). Bias fragments (bias/scale) in registers, loaded once per block.
// Softmax folds scale: e = expf(scale*(acc - max)).
// ---------------------------------------------------------------------------
#define AST 40
#define WPB 8

__global__ __launch_bounds__(128) void attn_tc(
    const __half* __restrict__ qkv,
    const float* __restrict__ bias_full,
    __half* __restrict__ out)
{
    // [stage][tensor][row][col] ; tensor: 0=Q 1=K 2=V
    __shared__ __align__(16) __half Ts[3][3][64][AST];

    const int bg   = blockIdx.x;          // window group (8 windows)
    const int h    = blockIdx.y;
    const int tid  = threadIdx.x;
    const int wrp  = tid >> 5;
    const int lane = tid & 31;
    const int g    = lane >> 2;
    const int c    = lane & 3;

    // Zero pad rows 49..63 (all stages/tensors): 3*3*15*4 = 540 16B chunks
    {
        const uint4 z = {0, 0, 0, 0};
        for (int idx = tid; idx < 540; idx += 128) {
            const int s  = idx / 180;
            const int r0 = idx - s * 180;
            const int t  = r0 / 60;
            const int r1 = r0 - t * 60;
            const int rr = 49 + (r1 >> 2);
            const int ch = r1 & 3;
            *(uint4*)&Ts[s][t][rr][ch * 8] = z;
        }
    }

    // Load bias fragments (bias/scale, fp32) once: rows 16w+g / 16w+8+g
    float bfr[8][4];
    {
        const float* bh = bias_full + h * 4096;
#pragma unroll
        for (int nt = 0; nt < 8; nt++) {
            const float2 b0 = *(const float2*)&bh[(16 * wrp + g) * 64 + 8 * nt + 2 * c];
            const float2 b1 = *(const float2*)&bh[(16 * wrp + 8 + g) * 64 + 8 * nt + 2 * c];
            bfr[nt][0] = b0.x; bfr[nt][1] = b0.y;
            bfr[nt][2] = b1.x; bfr[nt][3] = b1.y;
        }
    }

    // Stage issuer: window win -> stage s. 49 rows x 3 tensors x 4 chunks = 588
#define ATT_ISSUE(s, win)                                                              \
    do {                                                                               \
        const size_t rowbase = (size_t)((win) * NTOK) * QKVCOL + h * HDIM;             \
        for (int idx = tid; idx < 588; idx += 128) {                                   \
            const int n   = idx / 12;                                                  \
            const int rem = idx - n * 12;                                              \
            const int t   = rem >> 2;                                                  \
            const int ch  = rem & 3;                                                   \
            cp16(&Ts[s][t][n][ch * 8],                                                 \
                 qkv + rowbase + (size_t)n * QKVCOL + t * CDIM + ch * 8);              \
        }                                                                              \
    } while (0)

    const int b0 = bg * WPB;
    ATT_ISSUE(0, b0 + 0);
    asm volatile("cp.async.commit_group;");
    ATT_ISSUE(1, b0 + 1);
    asm volatile("cp.async.commit_group;");

    int buf = 0;
    for (int w = 0; w < WPB; w++) {
        asm volatile("cp.async.wait_group 1;");
        __syncthreads();
        if (w + 2 < WPB) {
            int nb = buf + 2; if (nb >= 3) nb -= 3;
            ATT_ISSUE(nb, b0 + w + 2);
        }
        asm volatile("cp.async.commit_group;");

        const int b = b0 + w;

        // ---- S = Q @ K^T (raw, unscaled); acc init = bias/scale ----
        float acc[8][4];
#pragma unroll
        for (int nt = 0; nt < 8; nt++) {
            acc[nt][0] = bfr[nt][0]; acc[nt][1] = bfr[nt][1];
            acc[nt][2] = bfr[nt][2]; acc[nt][3] = bfr[nt][3];
        }
#pragma unroll
        for (int kt = 0; kt < 2; kt++) {
            const int k0 = kt * 16;
            unsigned af[4];
            ldsm_x4(af[0], af[1], af[2], af[3],
                    &Ts[buf][0][16 * wrp + (lane & 15)][k0 + (lane >> 4) * 8]);
            unsigned bf[4][4];
#pragma unroll
            for (int ntg = 0; ntg < 4; ntg++) {
                const int rr = 16 * ntg + (lane & 7) + ((lane >> 4) & 1) * 8;
                const int cc = k0 + ((lane >> 3) & 1) * 8;
                ldsm_x4(bf[ntg][0], bf[ntg][1], bf[ntg][2], bf[ntg][3], &Ts[buf][1][rr][cc]);
            }
#pragma unroll
            for (int nt = 0; nt < 8; nt++)
                mma_f16(acc[nt], af,
                        bf[nt >> 1][(nt & 1) * 2], bf[nt >> 1][(nt & 1) * 2 + 1]);
        }

        // ---- Softmax with folded scale ----
        float inv[2];
#pragma unroll
        for (int rh = 0; rh < 2; rh++) {
            float m = -1e30f;
#pragma unroll
            for (int nt = 0; nt < 8; nt++) {
                m = fmaxf(m, acc[nt][2 * rh]);
                m = fmaxf(m, acc[nt][2 * rh + 1]);
            }
            m = fmaxf(m, __shfl_xor_sync(0xffffffffu, m, 1));
            m = fmaxf(m, __shfl_xor_sync(0xffffffffu, m, 2));
            const float em = m * ATT_SCALE;
            float s = 0.0f;
#pragma unroll
            for (int nt = 0; nt < 8; nt++) {
                const float e0 = __expf(fmaf(acc[nt][2 * rh],     ATT_SCALE, -em));
                const float e1 = __expf(fmaf(acc[nt][2 * rh + 1], ATT_SCALE, -em));
                acc[nt][2 * rh]     = e0;
                acc[nt][2 * rh + 1] = e1;
                s += e0 + e1;
            }
            s += __shfl_xor_sync(0xffffffffu, s, 1);
            s += __shfl_xor_sync(0xffffffffu, s, 2);
            inv[rh] = __fdividef(1.0f, s);
        }

        // ---- P fragments ----
        unsigned pa[4][4];
#pragma unroll
        for (int kt = 0; kt < 4; kt++) {
            pa[kt][0] = pack2h(acc[2 * kt][0],     acc[2 * kt][1]);
            pa[kt][1] = pack2h(acc[2 * kt][2],     acc[2 * kt][3]);
            pa[kt][2] = pack2h(acc[2 * kt + 1][0], acc[2 * kt + 1][1]);
            pa[kt][3] = pack2h(acc[2 * kt + 1][2], acc[2 * kt + 1][3]);
        }

        // ---- O = P @ V ----
        float oacc[4][4];
#pragma unroll
        for (int nt = 0; nt < 4; nt++)
#pragma unroll
            for (int r = 0; r < 4; r++) oacc[nt][r] = 0.0f;

#pragma unroll
        for (int kt = 0; kt < 4; kt++) {
            unsigned bv[2][4];
#pragma unroll
            for (int ntg = 0; ntg < 2; ntg++) {
                const int rr = 16 * kt + (lane & 15);
                const int cc = 16 * ntg + (lane >> 4) * 8;
                ldsm_x4_t(bv[ntg][0], bv[ntg][1], bv[ntg][2], bv[ntg][3], &Ts[buf][2][rr][cc]);
            }
#pragma unroll
            for (int nt = 0; nt < 4; nt++)
                mma_f16(oacc[nt], pa[kt],
                        bv[nt >> 1][(nt & 1) * 2], bv[nt >> 1][(nt & 1) * 2 + 1]);
        }

        // ---- Normalize + store ----
        const int i0 = 16 * wrp + g;
        const int i1 = i0 + 8;
#pragma unroll
        for (int nt = 0; nt < 4; nt++) {
            const int col = 8 * nt + 2 * c;
            if (i0 < NTOK) {
                *(__half2*)&out[(size_t)(b * NTOK + i0) * CDIM + h * HDIM + col] =
                    __floats2half2_rn(oacc[nt][0] * inv[0], oacc[nt][1] * inv[0]);
            }
            if (i1 < NTOK) {
                *(__half2*)&out[(size_t)(b * NTOK + i1) * CDIM + h * HDIM + col] =
                    __floats2half2_rn(oacc[nt][2] * inv[1], oacc[nt][3] * inv[1]);
            }
        }

        buf++; if (buf >= 3) buf = 0;
    }
}

// ---------------------------------------------------------------------------
extern "C" void kernel_launch(void* const* d_in, const int* in_sizes, int n_in,
                              void* d_out, int out_size)
{
    const float* x          = (const float*)d_in[0];
    const float* w_qkv      = (const float*)d_in[1];
    const float* b_qkv      = (const float*)d_in[2];
    const float* w_proj     = (const float*)d_in[3];
    const float* b_proj     = (const float*)d_in[4];
    const float* bias_table = (const float*)d_in[5];
    float* out = (float*)d_out;

    __half *xh, *wqkvh, *wprojh, *qkvh, *atth;
    float* biasf;
    cudaGetSymbolAddress((void**)&xh,     g_xh);
    cudaGetSymbolAddress((void**)&wqkvh,  g_wqkvh);
    cudaGetSymbolAddress((void**)&wprojh, g_wprojh);
    cudaGetSymbolAddress((void**)&qkvh,   g_qkvh);
    cudaGetSymbolAddress((void**)&atth,   g_atth);
    cudaGetSymbolAddress((void**)&biasf,  g_bias);

    cudaFuncSetAttribute(gemm_f16<true>,  cudaFuncAttributeMaxDynamicSharedMemorySize, GSMEM);
    cudaFuncSetAttribute(gemm_f16<false>, cudaFuncAttributeMaxDynamicSharedMemorySize, GSMEM);

    // 0) conversions + bias build
    {
        const int n4x = MROWS * CDIM / 4;
        f32_to_f16<<<(n4x + 255) / 256, 256>>>(x, xh, n4x);
        const int n4q = CDIM * QKVCOL / 4;
        f32_to_f16<<<(n4q + 255) / 256, 256>>>(w_qkv, wqkvh, n4q);
        const int n4p = CDIM * CDIM / 4;
        f32_to_f16<<<(n4p + 255) / 256, 256>>>(w_proj, wprojh, n4p);
        build_bias<<<(HEADS * 64 * 64 + 1023) / 1024, 1024>>>(bias_table, biasf);
    }
    // 1) QKV = x @ w_qkv + b_qkv (fp16 out)
    {
        dim3 grid(QKVCOL / BN, MROWS / BM);   // (9, 1568)
        gemm_f16<true><<<grid, 256, GSMEM>>>(xh, wqkvh, b_qkv, qkvh, MROWS, QKVCOL, CDIM);
    }
    // 2) Attention v3: 8 windows/block, cp.async pipelined
    {
        dim3 grid(NWIN / WPB, HEADS);         // (512, 12)
        attn_tc<<<grid, 128>>>(qkvh, biasf, atth);
    }
    // 3) out = att @ w_proj + b_proj (fp32 out)
    {
        dim3 grid(CDIM / BN, MROWS / BM);     // (3, 1568)
        gemm_f16<false><<<grid, 256, GSMEM>>>(atth, wprojh, b_proj, out, MROWS, CDIM, CDIM);
    }
}